// round 4
// baseline (speedup 1.0000x reference)
#include <cuda_runtime.h>
#include <cuda_bf16.h>
#include <math.h>
#include <cstdint>

#define H 32
#define DM 4096
#define DK 128
#define SQ 1024
#define LTOT 4096
#define MAXSEQ 8192
#define RSQRT_DK 0.08838834764831845f

// GEMM tiling: CTA tile MT x NT (MT+NT = 384), warp tile 64x64, 8 warps, BK=32, 3 stages
#define STAGES 3
#define BKT 32
#define ROWB 80                        // 64B data + 16B pad per k-slice row
#define STAGEB ((2 * 128 + 2 * 256) * ROWB)   // 61440, same for 128/256 and 256/128
#define SMEM_DYN (STAGES * STAGEB)            // 184320

// ============================ scratch (device globals) ============================
__device__ __align__(16) __nv_bfloat16 g_Xh[(size_t)SQ * DM], g_Xl[(size_t)SQ * DM];
__device__ __align__(16) __nv_bfloat16 g_Wqt_h[(size_t)H * DK * DM], g_Wqt_l[(size_t)H * DK * DM];
__device__ __align__(16) __nv_bfloat16 g_Kh[(size_t)H * LTOT * DK], g_Kl[(size_t)H * LTOT * DK];
__device__ __align__(16) __nv_bfloat16 g_Qh[(size_t)H * SQ * DK], g_Ql[(size_t)H * SQ * DK];
__device__ __align__(16) __nv_bfloat16 g_Ph[(size_t)H * SQ * LTOT], g_Pl[(size_t)H * SQ * LTOT];
__device__ __align__(16) __nv_bfloat16 g_Vth[(size_t)H * DK * LTOT], g_Vtl[(size_t)H * DK * LTOT];
__device__ __align__(16) __nv_bfloat16 g_Ch[(size_t)SQ * DM], g_Cl[(size_t)SQ * DM];
__device__ __align__(16) __nv_bfloat16 g_Woth[(size_t)DM * DM], g_Wotl[(size_t)DM * DM];
__device__ float g_inv[H * LTOT];
__device__ float g_kn[H * DK], g_vn[H * DK];

// ============================ helpers ============================
__device__ __forceinline__ uint32_t smem_to_u32(const void* p) {
    uint32_t a;
    asm("{ .reg .u64 t; cvta.to.shared.u64 t, %1; cvt.u32.u64 %0, t; }" : "=r"(a) : "l"(p));
    return a;
}

__device__ __forceinline__ void ldm_x4(uint32_t (&r)[4], uint32_t addr) {
    asm volatile("ldmatrix.sync.aligned.m8n8.x4.shared.b16 {%0,%1,%2,%3}, [%4];"
                 : "=r"(r[0]), "=r"(r[1]), "=r"(r[2]), "=r"(r[3]) : "r"(addr));
}

__device__ __forceinline__ void mma16816(float (&d)[4], const uint32_t (&a)[4],
                                         uint32_t b0, uint32_t b1) {
    asm volatile(
        "mma.sync.aligned.m16n8k16.row.col.f32.bf16.bf16.f32 "
        "{%0,%1,%2,%3}, {%4,%5,%6,%7}, {%8,%9}, {%0,%1,%2,%3};"
        : "+f"(d[0]), "+f"(d[1]), "+f"(d[2]), "+f"(d[3])
        : "r"(a[0]), "r"(a[1]), "r"(a[2]), "r"(a[3]), "r"(b0), "r"(b1));
}

__device__ __forceinline__ void cp16(uint32_t s, const void* g) {
    asm volatile("cp.async.ca.shared.global [%0], [%1], 16;" :: "r"(s), "l"(g));
}
#define CP_COMMIT() asm volatile("cp.async.commit_group;" ::: "memory")
#define CP_WAIT1()  asm volatile("cp.async.wait_group 1;" ::: "memory")

__device__ __forceinline__ void split_bf16(float v, __nv_bfloat16& hi, __nv_bfloat16& lo) {
    hi = __float2bfloat16(v);
    lo = __float2bfloat16(v - __bfloat162float(hi));
}

// ============================ GEMM mainloop ============================
// acc[4][8][4] += sum over K of (Ah+Al)[m][k] * (Bh+Bl)[n][k], dropping Al*Bl.
// CTA tile MT x NT, warp tile 64x64. A: MT rows x K (lda); B: NT rows x K (ldb); k-major bf16.
template <int MT, int NT>
__device__ __forceinline__ void gemm_main(
    const __nv_bfloat16* __restrict__ Ah, const __nv_bfloat16* __restrict__ Al,
    const __nv_bfloat16* __restrict__ Bh, const __nv_bfloat16* __restrict__ Bl,
    int lda, int ldb, int ktiles, char* sm, float (&acc)[4][8][4])
{
    constexpr int AMATB = MT * ROWB;
    constexpr int BMATB = NT * ROWB;
    constexpr int WN = NT / 64;
    const int tid = threadIdx.x;
    const int wid = tid >> 5, lane = tid & 31;
    const int wm = wid / WN, wn = wid % WN;
    uint32_t smb = smem_to_u32(sm);

#pragma unroll
    for (int mf = 0; mf < 4; mf++)
#pragma unroll
        for (int nf = 0; nf < 8; nf++)
#pragma unroll
            for (int i = 0; i < 4; i++) acc[mf][nf][i] = 0.f;

    auto load_stage = [&](int slot, int c) {
        constexpr int ACH = MT * 4;          // 16B chunks per A matrix
        constexpr int BCH = NT * 4;
        constexpr int TOT = 2 * ACH + 2 * BCH;   // 3072
#pragma unroll
        for (int j = 0; j < TOT / 256; j++) {
            int i = tid + j * 256;
            const __nv_bfloat16* src;
            int ld;
            uint32_t moff;
            int li;
            if (i < ACH)            { src = Ah; ld = lda; moff = 0;                 li = i; }
            else if (i < 2 * ACH)   { src = Al; ld = lda; moff = AMATB;             li = i - ACH; }
            else if (i < 2 * ACH + BCH) { src = Bh; ld = ldb; moff = 2 * AMATB;     li = i - 2 * ACH; }
            else                    { src = Bl; ld = ldb; moff = 2 * AMATB + BMATB; li = i - 2 * ACH - BCH; }
            int row = li >> 2, cc = li & 3;
            const void* g = src + (size_t)row * ld + (size_t)c * BKT + cc * 8;
            uint32_t s = smb + slot * STAGEB + moff + row * ROWB + cc * 16;
            cp16(s, g);
        }
        CP_COMMIT();
    };

    const uint32_t lrow = (uint32_t)(lane & 15);
    const uint32_t lcol = (uint32_t)((lane >> 4) & 1) * 16;
    const uint32_t arow = (uint32_t)(wm * 64 + lrow) * ROWB;
    const uint32_t brow = (uint32_t)(wn * 64 + lrow) * ROWB;

    auto compute = [&](int slot) {
        uint32_t base = smb + slot * STAGEB;
#pragma unroll
        for (int ks = 0; ks < 2; ks++) {
            uint32_t koff = ks * 32 + lcol;
            uint32_t ah[4][4], al[4][4], bh[4][4], bl[4][4];
#pragma unroll
            for (int mf = 0; mf < 4; mf++) {
                uint32_t a = base + arow + mf * (16 * ROWB) + koff;
                ldm_x4(ah[mf], a);
                ldm_x4(al[mf], a + AMATB);
            }
#pragma unroll
            for (int nb = 0; nb < 4; nb++) {
                uint32_t b = base + 2 * AMATB + brow + nb * (16 * ROWB) + koff;
                ldm_x4(bh[nb], b);
                ldm_x4(bl[nb], b + BMATB);
            }
#pragma unroll
            for (int mf = 0; mf < 4; mf++)
#pragma unroll
                for (int nf = 0; nf < 8; nf++) {
                    int nb = nf >> 1, sel = nf & 1;
                    mma16816(acc[mf][nf], ah[mf], bh[nb][sel], bh[nb][2 + sel]);
                    mma16816(acc[mf][nf], ah[mf], bl[nb][sel], bl[nb][2 + sel]);
                    mma16816(acc[mf][nf], al[mf], bh[nb][sel], bh[nb][2 + sel]);
                }
        }
    };

#pragma unroll 1
    for (int s = 0; s < STAGES - 1; s++) {
        if (s < ktiles) load_stage(s, s);
        else CP_COMMIT();
    }
#pragma unroll 1
    for (int c = 0; c < ktiles; c++) {
        CP_WAIT1();
        __syncthreads();
        int nxt = c + STAGES - 1;
        if (nxt < ktiles) load_stage(nxt % STAGES, nxt);
        else CP_COMMIT();
        compute(c % STAGES);
    }
}

// epilogue coordinate helpers (warp tile 64x64)
#define EPI_COORDS(WN_) \
    const int tid = threadIdx.x; \
    const int wid = tid >> 5, lane = tid & 31; \
    const int wm = wid / (WN_), wn = wid % (WN_); \
    const int g = lane >> 2, t2 = (lane & 3) * 2;

// ============================ GEMM kernels ============================
// Q projection: MT=128 (s rows), NT=256 (2 heads x 128 dk)
__global__ void __launch_bounds__(256, 1) k_qproj(const float* __restrict__ bq) {
    extern __shared__ char sm[];
    int h2 = blockIdx.x, mt = blockIdx.y;
    float acc[4][8][4];
    size_t boff = (size_t)(2 * h2) * DK * DM;
    gemm_main<128, 256>(g_Xh + (size_t)mt * 128 * DM, g_Xl + (size_t)mt * 128 * DM,
                        g_Wqt_h + boff, g_Wqt_l + boff, DM, DM, DM / BKT, sm, acc);
    EPI_COORDS(4);
#pragma unroll
    for (int mf = 0; mf < 4; mf++)
#pragma unroll
        for (int nf = 0; nf < 8; nf++) {
            int col = wn * 64 + nf * 8 + t2;
            int head = 2 * h2 + (col >> 7), k = col & 127;
            float b0 = bq[head * DK + k], b1 = bq[head * DK + k + 1];
            int r0 = wm * 64 + mf * 16 + g;
#pragma unroll
            for (int half = 0; half < 2; half++) {
                int r = r0 + half * 8;
                float v0 = acc[mf][nf][half * 2 + 0] + b0;
                float v1 = acc[mf][nf][half * 2 + 1] + b1;
                __nv_bfloat16 h0, l0, h1, l1;
                split_bf16(v0, h0, l0); split_bf16(v1, h1, l1);
                size_t o = ((size_t)head * SQ + mt * 128 + r) * DK + k;
                *(__nv_bfloat162*)&g_Qh[o] = __halves2bfloat162(h0, h1);
                *(__nv_bfloat162*)&g_Ql[o] = __halves2bfloat162(l0, l1);
            }
        }
}

// scores: MT=128 (s), NT=256 (l), K=128
__global__ void __launch_bounds__(256, 1) k_scores() {
    extern __shared__ char sm[];
    int nt = blockIdx.x, mt = blockIdx.y, h = blockIdx.z;
    float acc[4][8][4];
    size_t aoff = ((size_t)h * SQ + (size_t)mt * 128) * DK;
    size_t boff = ((size_t)h * LTOT + (size_t)nt * 256) * DK;
    gemm_main<128, 256>(g_Qh + aoff, g_Ql + aoff, g_Kh + boff, g_Kl + boff,
                        DK, DK, DK / BKT, sm, acc);
    EPI_COORDS(4);
    size_t rb = (size_t)h * SQ + (size_t)mt * 128;
#pragma unroll
    for (int mf = 0; mf < 4; mf++)
#pragma unroll
        for (int nf = 0; nf < 8; nf++) {
            int col = wn * 64 + nf * 8 + t2;
            int r0 = wm * 64 + mf * 16 + g;
#pragma unroll
            for (int half = 0; half < 2; half++) {
                int r = r0 + half * 8;
                float v0 = __expf(acc[mf][nf][half * 2 + 0] * RSQRT_DK);
                float v1 = __expf(acc[mf][nf][half * 2 + 1] * RSQRT_DK);
                __nv_bfloat16 h0, l0, h1, l1;
                split_bf16(v0, h0, l0); split_bf16(v1, h1, l1);
                size_t o = (rb + r) * LTOT + (size_t)nt * 256 + col;
                *(__nv_bfloat162*)&g_Ph[o] = __halves2bfloat162(h0, h1);
                *(__nv_bfloat162*)&g_Pl[o] = __halves2bfloat162(l0, l1);
            }
        }
}

// ctx: MT=256 (s), NT=128 (dk), K=4096
__global__ void __launch_bounds__(256, 1) k_ctx() {
    extern __shared__ char sm[];
    int mt = blockIdx.x, h = blockIdx.y;
    float acc[4][8][4];
    size_t aoff = ((size_t)h * SQ + (size_t)mt * 256) * LTOT;
    size_t boff = (size_t)h * DK * LTOT;
    gemm_main<256, 128>(g_Ph + aoff, g_Pl + aoff, g_Vth + boff, g_Vtl + boff,
                        LTOT, LTOT, LTOT / BKT, sm, acc);
    EPI_COORDS(2);
#pragma unroll
    for (int mf = 0; mf < 4; mf++)
#pragma unroll
        for (int nf = 0; nf < 8; nf++) {
            int col = wn * 64 + nf * 8 + t2;
            int r0 = wm * 64 + mf * 16 + g;
#pragma unroll
            for (int half = 0; half < 2; half++) {
                int r = r0 + half * 8;
                float v0 = acc[mf][nf][half * 2 + 0];
                float v1 = acc[mf][nf][half * 2 + 1];
                __nv_bfloat16 h0, l0, h1, l1;
                split_bf16(v0, h0, l0); split_bf16(v1, h1, l1);
                size_t o = (size_t)(mt * 256 + r) * DM + (size_t)h * DK + col;
                *(__nv_bfloat162*)&g_Ch[o] = __halves2bfloat162(h0, h1);
                *(__nv_bfloat162*)&g_Cl[o] = __halves2bfloat162(l0, l1);
            }
        }
}

// out: MT=128 (s), NT=256 (d_out), K=4096
__global__ void __launch_bounds__(256, 1) k_out(const float* __restrict__ bo,
                                                float* __restrict__ out) {
    extern __shared__ char sm[];
    int nt = blockIdx.x, mt = blockIdx.y;
    float acc[4][8][4];
    gemm_main<128, 256>(g_Ch + (size_t)mt * 128 * DM, g_Cl + (size_t)mt * 128 * DM,
                        g_Woth + (size_t)nt * 256 * DM, g_Wotl + (size_t)nt * 256 * DM,
                        DM, DM, DM / BKT, sm, acc);
    EPI_COORDS(4);
    const float* bop = bo + nt * 256;
#pragma unroll
    for (int mf = 0; mf < 4; mf++)
#pragma unroll
        for (int nf = 0; nf < 8; nf++) {
            int col = wn * 64 + nf * 8 + t2;
            float b0 = bop[col], b1 = bop[col + 1];
            int r0 = wm * 64 + mf * 16 + g;
#pragma unroll
            for (int half = 0; half < 2; half++) {
                int r = r0 + half * 8;
                float2 v;
                v.x = acc[mf][nf][half * 2 + 0] + b0;
                v.y = acc[mf][nf][half * 2 + 1] + b1;
                *(float2*)&out[(size_t)(mt * 128 + r) * DM + (size_t)nt * 256 + col] = v;
            }
        }
}

// ============================ prep kernels ============================
__global__ void knv_kernel(const float* __restrict__ x,
                           const float* __restrict__ Wk, const float* __restrict__ bk,
                           const float* __restrict__ Wv, const float* __restrict__ bv) {
    int h = blockIdx.x;
    int k = threadIdx.x;
    const float* xl = x + (size_t)(SQ - 1) * DM;
    const float* wk = Wk + (size_t)h * DM * DK + k;
    const float* wv = Wv + (size_t)h * DM * DK + k;
    float aK = 0.f, aV = 0.f;
#pragma unroll 4
    for (int d = 0; d < DM; d++) {
        float xv = xl[d];
        aK += xv * wk[(size_t)d * DK];
        aV += xv * wv[(size_t)d * DK];
    }
    g_kn[h * DK + k] = aK + bk[h * DK + k];
    g_vn[h * DK + k] = aV + bv[h * DK + k];
}

__global__ void conv_x(const float* __restrict__ x) {
    size_t i = (size_t)blockIdx.x * 256 + threadIdx.x;
    __nv_bfloat16 hi, lo;
    split_bf16(x[i], hi, lo);
    g_Xh[i] = hi; g_Xl[i] = lo;
}

__global__ void conv_keys(const float* __restrict__ kc, const int* __restrict__ posp) {
    size_t i = (size_t)blockIdx.x * 256 + threadIdx.x;   // over H*LTOT*DK
    int h = (int)(i / ((size_t)LTOT * DK));
    int rem = (int)(i % ((size_t)LTOT * DK));
    int l = rem / DK, dk = rem % DK;
    int pos = posp[0];
    float v = (l == pos) ? g_kn[h * DK + dk] : kc[((size_t)h * MAXSEQ + l) * DK + dk];
    __nv_bfloat16 hi, lo;
    split_bf16(v, hi, lo);
    g_Kh[i] = hi; g_Kl[i] = lo;
}

// transpose Wq[h, d, dk] -> Wqt[h, dk, d], bf16 split
__global__ void tconv_wq(const float* __restrict__ W) {
    __shared__ float t[32][33];
    int h = blockIdx.z;
    int c0 = blockIdx.x * 32;   // dk
    int r0 = blockIdx.y * 32;   // d
    int tx = threadIdx.x, ty = threadIdx.y;
    const float* in = W + (size_t)h * DM * DK;
#pragma unroll
    for (int i = 0; i < 32; i += 8)
        t[ty + i][tx] = in[(size_t)(r0 + ty + i) * DK + c0 + tx];
    __syncthreads();
    __nv_bfloat16* oh = g_Wqt_h + (size_t)h * DK * DM;
    __nv_bfloat16* ol = g_Wqt_l + (size_t)h * DK * DM;
#pragma unroll
    for (int i = 0; i < 32; i += 8) {
        float v = t[tx][ty + i];
        __nv_bfloat16 hi, lo;
        split_bf16(v, hi, lo);
        size_t o = (size_t)(c0 + ty + i) * DM + r0 + tx;
        oh[o] = hi; ol[o] = lo;
    }
}

// transpose Wo[d_in, d_out] -> Wot[d_out, d_in], bf16 split
__global__ void tconv_wo(const float* __restrict__ W) {
    __shared__ float t[32][33];
    int c0 = blockIdx.x * 32;   // d_out
    int r0 = blockIdx.y * 32;   // d_in
    int tx = threadIdx.x, ty = threadIdx.y;
#pragma unroll
    for (int i = 0; i < 32; i += 8)
        t[ty + i][tx] = W[(size_t)(r0 + ty + i) * DM + c0 + tx];
    __syncthreads();
#pragma unroll
    for (int i = 0; i < 32; i += 8) {
        float v = t[tx][ty + i];
        __nv_bfloat16 hi, lo;
        split_bf16(v, hi, lo);
        size_t o = (size_t)(c0 + ty + i) * DM + r0 + tx;
        g_Woth[o] = hi; g_Wotl[o] = lo;
    }
}

// Vt[h, dk, l] = inv[h,l] * V[h,l,dk] (with l==pos row from g_vn), transposed + split
__global__ void tconv_vt(const float* __restrict__ vc, const int* __restrict__ posp) {
    __shared__ float t[32][33];
    int h = blockIdx.z;
    int c0 = blockIdx.x * 32;   // dk
    int r0 = blockIdx.y * 32;   // l
    int tx = threadIdx.x, ty = threadIdx.y;
    int pos = posp[0];
#pragma unroll
    for (int i = 0; i < 32; i += 8) {
        int l = r0 + ty + i, dk = c0 + tx;
        float v = (l == pos) ? g_vn[h * DK + dk] : vc[((size_t)h * MAXSEQ + l) * DK + dk];
        t[ty + i][tx] = v * g_inv[h * LTOT + l];
    }
    __syncthreads();
    __nv_bfloat16* oh = g_Vth + (size_t)h * DK * LTOT;
    __nv_bfloat16* ol = g_Vtl + (size_t)h * DK * LTOT;
#pragma unroll
    for (int i = 0; i < 32; i += 8) {
        float v = t[tx][ty + i];
        __nv_bfloat16 hi, lo;
        split_bf16(v, hi, lo);
        size_t o = (size_t)(c0 + ty + i) * LTOT + r0 + tx;
        oh[o] = hi; ol[o] = lo;
    }
}

// g_inv[h,l] = 1 / sum_s (Ph + Pl)
__global__ void colsum_kernel() {
    int idx = blockIdx.x * 256 + threadIdx.x;   // over H*LTOT
    int h = idx / LTOT, l = idx % LTOT;
    const __nv_bfloat16* ph = g_Ph + (size_t)h * SQ * LTOT + l;
    const __nv_bfloat16* pl = g_Pl + (size_t)h * SQ * LTOT + l;
    float s0 = 0.f, s1 = 0.f, s2 = 0.f, s3 = 0.f;
    for (int i = 0; i < SQ; i += 4) {
        s0 += __bfloat162float(ph[(size_t)(i + 0) * LTOT]) + __bfloat162float(pl[(size_t)(i + 0) * LTOT]);
        s1 += __bfloat162float(ph[(size_t)(i + 1) * LTOT]) + __bfloat162float(pl[(size_t)(i + 1) * LTOT]);
        s2 += __bfloat162float(ph[(size_t)(i + 2) * LTOT]) + __bfloat162float(pl[(size_t)(i + 2) * LTOT]);
        s3 += __bfloat162float(ph[(size_t)(i + 3) * LTOT]) + __bfloat162float(pl[(size_t)(i + 3) * LTOT]);
    }
    g_inv[idx] = 1.0f / ((s0 + s1) + (s2 + s3));
}

// ============================ launch ============================
extern "C" void kernel_launch(void* const* d_in, const int* in_sizes, int n_in,
                              void* d_out, int out_size) {
    const float* x   = (const float*)d_in[0];
    const float* kc  = (const float*)d_in[1];
    const float* vc  = (const float*)d_in[2];
    const float* Wq  = (const float*)d_in[3];
    const float* bq  = (const float*)d_in[4];
    const float* Wk  = (const float*)d_in[5];
    const float* bk  = (const float*)d_in[6];
    const float* Wv  = (const float*)d_in[7];
    const float* bv  = (const float*)d_in[8];
    const float* Wo  = (const float*)d_in[9];
    const float* bo  = (const float*)d_in[10];
    const int*   pos = (const int*)d_in[11];
    float* out = (float*)d_out;

    cudaFuncSetAttribute(k_qproj,  cudaFuncAttributeMaxDynamicSharedMemorySize, SMEM_DYN);
    cudaFuncSetAttribute(k_scores, cudaFuncAttributeMaxDynamicSharedMemorySize, SMEM_DYN);
    cudaFuncSetAttribute(k_ctx,    cudaFuncAttributeMaxDynamicSharedMemorySize, SMEM_DYN);
    cudaFuncSetAttribute(k_out,    cudaFuncAttributeMaxDynamicSharedMemorySize, SMEM_DYN);

    knv_kernel<<<H, DK>>>(x, Wk, bk, Wv, bv);
    conv_x<<<(SQ * DM) / 256, 256>>>(x);
    tconv_wq<<<dim3(DK / 32, DM / 32, H), dim3(32, 8)>>>(Wq);
    tconv_wo<<<dim3(DM / 32, DM / 32), dim3(32, 8)>>>(Wo);
    conv_keys<<<(H * LTOT * DK) / 256, 256>>>(kc, pos);

    k_qproj<<<dim3(H / 2, SQ / 128), 256, SMEM_DYN>>>(bq);
    k_scores<<<dim3(LTOT / 256, SQ / 128, H), 256, SMEM_DYN>>>();
    colsum_kernel<<<(H * LTOT) / 256, 256>>>();
    tconv_vt<<<dim3(DK / 32, LTOT / 32, H), dim3(32, 8)>>>(vc, pos);
    k_ctx<<<dim3(SQ / 256, H), 256, SMEM_DYN>>>();
    k_out<<<dim3(DM / 256, SQ / 128), 256, SMEM_DYN>>>(bo, out);
}

// round 5
// speedup vs baseline: 1.0285x; 1.0285x over previous
#include <cuda_runtime.h>
#include <cuda_bf16.h>
#include <math.h>
#include <cstdint>

#define H 32
#define DM 4096
#define DK 128
#define SQ 1024
#define LTOT 4096
#define MAXSEQ 8192
#define RSQRT_DK 0.08838834764831845f

// GEMM tiling: CTA 128x128, warp tile 64x32 (2x4 warps), BK=32, 2 stages, 2 CTAs/SM
#define STAGES 2
#define BKT 32
#define ROWB 80                 // 64B data + 16B pad
#define MATB (128 * ROWB)       // 10240 B
#define STAGEB (4 * MATB)       // 40960 B (Ah, Al, Bh, Bl)
#define SMEM_DYN (STAGES * STAGEB)   // 81920

// ============================ scratch (device globals) ============================
__device__ __align__(16) __nv_bfloat16 g_Xh[(size_t)SQ * DM], g_Xl[(size_t)SQ * DM];
__device__ __align__(16) __nv_bfloat16 g_Wqt_h[(size_t)H * DK * DM], g_Wqt_l[(size_t)H * DK * DM];
__device__ __align__(16) __nv_bfloat16 g_Kh[(size_t)H * LTOT * DK], g_Kl[(size_t)H * LTOT * DK];
__device__ __align__(16) __nv_bfloat16 g_Qh[(size_t)H * SQ * DK], g_Ql[(size_t)H * SQ * DK];
__device__ __align__(16) __nv_bfloat16 g_Ph[(size_t)H * SQ * LTOT], g_Pl[(size_t)H * SQ * LTOT];
__device__ __align__(16) __nv_bfloat16 g_Vth[(size_t)H * DK * LTOT], g_Vtl[(size_t)H * DK * LTOT];
__device__ __align__(16) __nv_bfloat16 g_Ch[(size_t)SQ * DM], g_Cl[(size_t)SQ * DM];
__device__ __align__(16) __nv_bfloat16 g_Woth[(size_t)DM * DM], g_Wotl[(size_t)DM * DM];
__device__ float g_inv[H * LTOT];
__device__ float g_kn[H * DK], g_vn[H * DK];

// ============================ helpers ============================
__device__ __forceinline__ uint32_t smem_to_u32(const void* p) {
    uint32_t a;
    asm("{ .reg .u64 t; cvta.to.shared.u64 t, %1; cvt.u32.u64 %0, t; }" : "=r"(a) : "l"(p));
    return a;
}

__device__ __forceinline__ void ldm_x4(uint32_t (&r)[4], uint32_t addr) {
    asm volatile("ldmatrix.sync.aligned.m8n8.x4.shared.b16 {%0,%1,%2,%3}, [%4];"
                 : "=r"(r[0]), "=r"(r[1]), "=r"(r[2]), "=r"(r[3]) : "r"(addr));
}

__device__ __forceinline__ void mma16816(float (&d)[4], const uint32_t (&a)[4],
                                         uint32_t b0, uint32_t b1) {
    asm volatile(
        "mma.sync.aligned.m16n8k16.row.col.f32.bf16.bf16.f32 "
        "{%0,%1,%2,%3}, {%4,%5,%6,%7}, {%8,%9}, {%0,%1,%2,%3};"
        : "+f"(d[0]), "+f"(d[1]), "+f"(d[2]), "+f"(d[3])
        : "r"(a[0]), "r"(a[1]), "r"(a[2]), "r"(a[3]), "r"(b0), "r"(b1));
}

__device__ __forceinline__ void cp16(uint32_t s, const void* g) {
    asm volatile("cp.async.ca.shared.global [%0], [%1], 16;" :: "r"(s), "l"(g));
}
#define CP_COMMIT() asm volatile("cp.async.commit_group;" ::: "memory")
#define CP_WAIT1()  asm volatile("cp.async.wait_group 1;" ::: "memory")
#define CP_WAIT0()  asm volatile("cp.async.wait_group 0;" ::: "memory")

__device__ __forceinline__ void split_bf16(float v, __nv_bfloat16& hi, __nv_bfloat16& lo) {
    hi = __float2bfloat16(v);
    lo = __float2bfloat16(v - __bfloat162float(hi));
}

// ============================ GEMM mainloop ============================
// acc[4][4][4] += sum over K of (Ah+Al)[m][k] * (Bh+Bl)[n][k], dropping Al*Bl.
// CTA tile 128x128, warp tile 64x32. A: 128 x K (lda), B: 128 x K (ldb), k-major bf16.
__device__ __forceinline__ void gemm_main(
    const __nv_bfloat16* __restrict__ Ah, const __nv_bfloat16* __restrict__ Al,
    const __nv_bfloat16* __restrict__ Bh, const __nv_bfloat16* __restrict__ Bl,
    int lda, int ldb, int ktiles, char* sm, float (&acc)[4][4][4])
{
    const int tid = threadIdx.x;
    const int wid = tid >> 5, lane = tid & 31;
    const int wm = wid >> 2, wn = wid & 3;
    uint32_t smb = smem_to_u32(sm);

#pragma unroll
    for (int mf = 0; mf < 4; mf++)
#pragma unroll
        for (int nf = 0; nf < 4; nf++)
#pragma unroll
            for (int i = 0; i < 4; i++) acc[mf][nf][i] = 0.f;

    auto load_stage = [&](int slot, int c) {
#pragma unroll
        for (int j = 0; j < 8; j++) {
            int i = tid + j * 256;
            int mat = i >> 9;
            int rem = i & 511;
            int row = rem >> 2, cc = rem & 3;
            const __nv_bfloat16* src = (mat == 0) ? Ah : (mat == 1) ? Al
                                      : (mat == 2) ? Bh : Bl;
            int ld = (mat < 2) ? lda : ldb;
            const void* g = src + (size_t)row * ld + (size_t)c * BKT + cc * 8;
            uint32_t s = smb + slot * STAGEB + mat * MATB + row * ROWB + cc * 16;
            cp16(s, g);
        }
        CP_COMMIT();
    };

    const uint32_t lrow = (uint32_t)(lane & 15);
    const uint32_t lcol = (uint32_t)((lane >> 4) & 1) * 16;
    const uint32_t arow = (uint32_t)(wm * 64 + lrow) * ROWB;
    const uint32_t brow = (uint32_t)(wn * 32 + lrow) * ROWB;

    auto compute = [&](int slot) {
        uint32_t base = smb + slot * STAGEB;
#pragma unroll
        for (int ks = 0; ks < 2; ks++) {
            uint32_t koff = ks * 32 + lcol;
            uint32_t ah[4][4], al[4][4], bh[2][4], bl[2][4];
#pragma unroll
            for (int mf = 0; mf < 4; mf++) {
                uint32_t a = base + arow + mf * (16 * ROWB) + koff;
                ldm_x4(ah[mf], a);
                ldm_x4(al[mf], a + MATB);
            }
#pragma unroll
            for (int nb = 0; nb < 2; nb++) {
                uint32_t b = base + 2 * MATB + brow + nb * (16 * ROWB) + koff;
                ldm_x4(bh[nb], b);
                ldm_x4(bl[nb], b + MATB);
            }
            // term-major issue order: long dependency distance per accumulator
#pragma unroll
            for (int mf = 0; mf < 4; mf++)
#pragma unroll
                for (int nf = 0; nf < 4; nf++) {
                    int nb = nf >> 1, sel = nf & 1;
                    mma16816(acc[mf][nf], ah[mf], bh[nb][sel], bh[nb][2 + sel]);
                }
#pragma unroll
            for (int mf = 0; mf < 4; mf++)
#pragma unroll
                for (int nf = 0; nf < 4; nf++) {
                    int nb = nf >> 1, sel = nf & 1;
                    mma16816(acc[mf][nf], ah[mf], bl[nb][sel], bl[nb][2 + sel]);
                }
#pragma unroll
            for (int mf = 0; mf < 4; mf++)
#pragma unroll
                for (int nf = 0; nf < 4; nf++) {
                    int nb = nf >> 1, sel = nf & 1;
                    mma16816(acc[mf][nf], al[mf], bh[nb][sel], bh[nb][2 + sel]);
                }
        }
    };

    load_stage(0, 0);
#pragma unroll 1
    for (int c = 0; c < ktiles; c++) {
        if (c + 1 < ktiles) {
            load_stage((c + 1) & 1, c + 1);
            CP_WAIT1();
        } else {
            CP_WAIT0();
        }
        __syncthreads();      // chunk-c data visible to all warps
        compute(c & 1);
        __syncthreads();      // all warps done with slot (c&1) before it is overwritten
    }
}

// epilogue coordinate helpers (warp tile 64x32)
#define EPI_COORDS() \
    const int tid = threadIdx.x; \
    const int wid = tid >> 5, lane = tid & 31; \
    const int wm = wid >> 2, wn = wid & 3; \
    const int g = lane >> 2, t2 = (lane & 3) * 2;

// ============================ GEMM kernels ============================
__global__ void __launch_bounds__(256, 2) k_qproj(const float* __restrict__ bq) {
    extern __shared__ char sm[];
    int h = blockIdx.x, mt = blockIdx.y;
    float acc[4][4][4];
    gemm_main(g_Xh + (size_t)mt * 128 * DM, g_Xl + (size_t)mt * 128 * DM,
              g_Wqt_h + (size_t)h * DK * DM, g_Wqt_l + (size_t)h * DK * DM,
              DM, DM, DM / BKT, sm, acc);
    EPI_COORDS();
    const float* bqp = bq + h * DK;
    size_t rb = (size_t)h * SQ + (size_t)mt * 128;
#pragma unroll
    for (int mf = 0; mf < 4; mf++)
#pragma unroll
        for (int nf = 0; nf < 4; nf++) {
            int col = wn * 32 + nf * 8 + t2;
            float b0 = bqp[col], b1 = bqp[col + 1];
            int r0 = wm * 64 + mf * 16 + g;
#pragma unroll
            for (int half = 0; half < 2; half++) {
                int r = r0 + half * 8;
                float v0 = acc[mf][nf][half * 2 + 0] + b0;
                float v1 = acc[mf][nf][half * 2 + 1] + b1;
                __nv_bfloat16 h0, l0, h1, l1;
                split_bf16(v0, h0, l0); split_bf16(v1, h1, l1);
                size_t o = (rb + r) * DK + col;
                *(__nv_bfloat162*)&g_Qh[o] = __halves2bfloat162(h0, h1);
                *(__nv_bfloat162*)&g_Ql[o] = __halves2bfloat162(l0, l1);
            }
        }
}

__global__ void __launch_bounds__(256, 2) k_scores() {
    extern __shared__ char sm[];
    int nt = blockIdx.x, mt = blockIdx.y, h = blockIdx.z;
    float acc[4][4][4];
    size_t aoff = ((size_t)h * SQ + (size_t)mt * 128) * DK;
    size_t boff = ((size_t)h * LTOT + (size_t)nt * 128) * DK;
    gemm_main(g_Qh + aoff, g_Ql + aoff, g_Kh + boff, g_Kl + boff,
              DK, DK, DK / BKT, sm, acc);
    EPI_COORDS();
    size_t rb = (size_t)h * SQ + (size_t)mt * 128;
#pragma unroll
    for (int mf = 0; mf < 4; mf++)
#pragma unroll
        for (int nf = 0; nf < 4; nf++) {
            int col = wn * 32 + nf * 8 + t2;
            int r0 = wm * 64 + mf * 16 + g;
#pragma unroll
            for (int half = 0; half < 2; half++) {
                int r = r0 + half * 8;
                float v0 = __expf(acc[mf][nf][half * 2 + 0] * RSQRT_DK);
                float v1 = __expf(acc[mf][nf][half * 2 + 1] * RSQRT_DK);
                __nv_bfloat16 h0, l0, h1, l1;
                split_bf16(v0, h0, l0); split_bf16(v1, h1, l1);
                size_t o = (rb + r) * LTOT + (size_t)nt * 128 + col;
                *(__nv_bfloat162*)&g_Ph[o] = __halves2bfloat162(h0, h1);
                *(__nv_bfloat162*)&g_Pl[o] = __halves2bfloat162(l0, l1);
            }
        }
}

__global__ void __launch_bounds__(256, 2) k_ctx() {
    extern __shared__ char sm[];
    int mt = blockIdx.x, h = blockIdx.y;
    float acc[4][4][4];
    size_t aoff = ((size_t)h * SQ + (size_t)mt * 128) * LTOT;
    size_t boff = (size_t)h * DK * LTOT;
    gemm_main(g_Ph + aoff, g_Pl + aoff, g_Vth + boff, g_Vtl + boff,
              LTOT, LTOT, LTOT / BKT, sm, acc);
    EPI_COORDS();
#pragma unroll
    for (int mf = 0; mf < 4; mf++)
#pragma unroll
        for (int nf = 0; nf < 4; nf++) {
            int col = wn * 32 + nf * 8 + t2;
            int r0 = wm * 64 + mf * 16 + g;
#pragma unroll
            for (int half = 0; half < 2; half++) {
                int r = r0 + half * 8;
                float v0 = acc[mf][nf][half * 2 + 0];
                float v1 = acc[mf][nf][half * 2 + 1];
                __nv_bfloat16 h0, l0, h1, l1;
                split_bf16(v0, h0, l0); split_bf16(v1, h1, l1);
                size_t o = (size_t)(mt * 128 + r) * DM + (size_t)h * DK + col;
                *(__nv_bfloat162*)&g_Ch[o] = __halves2bfloat162(h0, h1);
                *(__nv_bfloat162*)&g_Cl[o] = __halves2bfloat162(l0, l1);
            }
        }
}

__global__ void __launch_bounds__(256, 2) k_out(const float* __restrict__ bo,
                                                float* __restrict__ out) {
    extern __shared__ char sm[];
    int nt = blockIdx.x, mt = blockIdx.y;
    float acc[4][4][4];
    gemm_main(g_Ch + (size_t)mt * 128 * DM, g_Cl + (size_t)mt * 128 * DM,
              g_Woth + (size_t)nt * 128 * DM, g_Wotl + (size_t)nt * 128 * DM,
              DM, DM, DM / BKT, sm, acc);
    EPI_COORDS();
    const float* bop = bo + nt * 128;
#pragma unroll
    for (int mf = 0; mf < 4; mf++)
#pragma unroll
        for (int nf = 0; nf < 4; nf++) {
            int col = wn * 32 + nf * 8 + t2;
            float b0 = bop[col], b1 = bop[col + 1];
            int r0 = wm * 64 + mf * 16 + g;
#pragma unroll
            for (int half = 0; half < 2; half++) {
                int r = r0 + half * 8;
                float2 v;
                v.x = acc[mf][nf][half * 2 + 0] + b0;
                v.y = acc[mf][nf][half * 2 + 1] + b1;
                *(float2*)&out[(size_t)(mt * 128 + r) * DM + (size_t)nt * 128 + col] = v;
            }
        }
}

// ============================ prep kernels ============================
__global__ void knv_kernel(const float* __restrict__ x,
                           const float* __restrict__ Wk, const float* __restrict__ bk,
                           const float* __restrict__ Wv, const float* __restrict__ bv) {
    int h = blockIdx.x;
    int k = threadIdx.x;
    const float* xl = x + (size_t)(SQ - 1) * DM;
    const float* wk = Wk + (size_t)h * DM * DK + k;
    const float* wv = Wv + (size_t)h * DM * DK + k;
    float aK = 0.f, aV = 0.f;
#pragma unroll 4
    for (int d = 0; d < DM; d++) {
        float xv = xl[d];
        aK += xv * wk[(size_t)d * DK];
        aV += xv * wv[(size_t)d * DK];
    }
    g_kn[h * DK + k] = aK + bk[h * DK + k];
    g_vn[h * DK + k] = aV + bv[h * DK + k];
}

__global__ void conv_x(const float* __restrict__ x) {
    size_t i = (size_t)blockIdx.x * 256 + threadIdx.x;
    __nv_bfloat16 hi, lo;
    split_bf16(x[i], hi, lo);
    g_Xh[i] = hi; g_Xl[i] = lo;
}

__global__ void conv_keys(const float* __restrict__ kc, const int* __restrict__ posp) {
    size_t i = (size_t)blockIdx.x * 256 + threadIdx.x;   // over H*LTOT*DK
    int h = (int)(i / ((size_t)LTOT * DK));
    int rem = (int)(i % ((size_t)LTOT * DK));
    int l = rem / DK, dk = rem % DK;
    int pos = posp[0];
    float v = (l == pos) ? g_kn[h * DK + dk] : kc[((size_t)h * MAXSEQ + l) * DK + dk];
    __nv_bfloat16 hi, lo;
    split_bf16(v, hi, lo);
    g_Kh[i] = hi; g_Kl[i] = lo;
}

// transpose Wq[h, d, dk] -> Wqt[h, dk, d], bf16 split
__global__ void tconv_wq(const float* __restrict__ W) {
    __shared__ float t[32][33];
    int h = blockIdx.z;
    int c0 = blockIdx.x * 32;   // dk
    int r0 = blockIdx.y * 32;   // d
    int tx = threadIdx.x, ty = threadIdx.y;
    const float* in = W + (size_t)h * DM * DK;
#pragma unroll
    for (int i = 0; i < 32; i += 8)
        t[ty + i][tx] = in[(size_t)(r0 + ty + i) * DK + c0 + tx];
    __syncthreads();
    __nv_bfloat16* oh = g_Wqt_h + (size_t)h * DK * DM;
    __nv_bfloat16* ol = g_Wqt_l + (size_t)h * DK * DM;
#pragma unroll
    for (int i = 0; i < 32; i += 8) {
        float v = t[tx][ty + i];
        __nv_bfloat16 hi, lo;
        split_bf16(v, hi, lo);
        size_t o = (size_t)(c0 + ty + i) * DM + r0 + tx;
        oh[o] = hi; ol[o] = lo;
    }
}

// transpose Wo[d_in, d_out] -> Wot[d_out, d_in], bf16 split
__global__ void tconv_wo(const float* __restrict__ W) {
    __shared__ float t[32][33];
    int c0 = blockIdx.x * 32;   // d_out
    int r0 = blockIdx.y * 32;   // d_in
    int tx = threadIdx.x, ty = threadIdx.y;
#pragma unroll
    for (int i = 0; i < 32; i += 8)
        t[ty + i][tx] = W[(size_t)(r0 + ty + i) * DM + c0 + tx];
    __syncthreads();
#pragma unroll
    for (int i = 0; i < 32; i += 8) {
        float v = t[tx][ty + i];
        __nv_bfloat16 hi, lo;
        split_bf16(v, hi, lo);
        size_t o = (size_t)(c0 + ty + i) * DM + r0 + tx;
        g_Woth[o] = hi; g_Wotl[o] = lo;
    }
}

// Vt[h, dk, l] = inv[h,l] * V[h,l,dk] (with l==pos row from g_vn), transposed + split
__global__ void tconv_vt(const float* __restrict__ vc, const int* __restrict__ posp) {
    __shared__ float t[32][33];
    int h = blockIdx.z;
    int c0 = blockIdx.x * 32;   // dk
    int r0 = blockIdx.y * 32;   // l
    int tx = threadIdx.x, ty = threadIdx.y;
    int pos = posp[0];
#pragma unroll
    for (int i = 0; i < 32; i += 8) {
        int l = r0 + ty + i, dk = c0 + tx;
        float v = (l == pos) ? g_vn[h * DK + dk] : vc[((size_t)h * MAXSEQ + l) * DK + dk];
        t[ty + i][tx] = v * g_inv[h * LTOT + l];
    }
    __syncthreads();
    __nv_bfloat16* oh = g_Vth + (size_t)h * DK * LTOT;
    __nv_bfloat16* ol = g_Vtl + (size_t)h * DK * LTOT;
#pragma unroll
    for (int i = 0; i < 32; i += 8) {
        float v = t[tx][ty + i];
        __nv_bfloat16 hi, lo;
        split_bf16(v, hi, lo);
        size_t o = (size_t)(c0 + ty + i) * LTOT + r0 + tx;
        oh[o] = hi; ol[o] = lo;
    }
}

// g_inv[h,l] = 1 / sum_s (Ph + Pl)
__global__ void colsum_kernel() {
    int idx = blockIdx.x * 256 + threadIdx.x;   // over H*LTOT
    int h = idx / LTOT, l = idx % LTOT;
    const __nv_bfloat16* ph = g_Ph + (size_t)h * SQ * LTOT + l;
    const __nv_bfloat16* pl = g_Pl + (size_t)h * SQ * LTOT + l;
    float s0 = 0.f, s1 = 0.f, s2 = 0.f, s3 = 0.f;
    for (int i = 0; i < SQ; i += 4) {
        s0 += __bfloat162float(ph[(size_t)(i + 0) * LTOT]) + __bfloat162float(pl[(size_t)(i + 0) * LTOT]);
        s1 += __bfloat162float(ph[(size_t)(i + 1) * LTOT]) + __bfloat162float(pl[(size_t)(i + 1) * LTOT]);
        s2 += __bfloat162float(ph[(size_t)(i + 2) * LTOT]) + __bfloat162float(pl[(size_t)(i + 2) * LTOT]);
        s3 += __bfloat162float(ph[(size_t)(i + 3) * LTOT]) + __bfloat162float(pl[(size_t)(i + 3) * LTOT]);
    }
    g_inv[idx] = 1.0f / ((s0 + s1) + (s2 + s3));
}

// ============================ launch ============================
extern "C" void kernel_launch(void* const* d_in, const int* in_sizes, int n_in,
                              void* d_out, int out_size) {
    const float* x   = (const float*)d_in[0];
    const float* kc  = (const float*)d_in[1];
    const float* vc  = (const float*)d_in[2];
    const float* Wq  = (const float*)d_in[3];
    const float* bq  = (const float*)d_in[4];
    const float* Wk  = (const float*)d_in[5];
    const float* bk  = (const float*)d_in[6];
    const float* Wv  = (const float*)d_in[7];
    const float* bv  = (const float*)d_in[8];
    const float* Wo  = (const float*)d_in[9];
    const float* bo  = (const float*)d_in[10];
    const int*   pos = (const int*)d_in[11];
    float* out = (float*)d_out;

    cudaFuncSetAttribute(k_qproj,  cudaFuncAttributeMaxDynamicSharedMemorySize, SMEM_DYN);
    cudaFuncSetAttribute(k_scores, cudaFuncAttributeMaxDynamicSharedMemorySize, SMEM_DYN);
    cudaFuncSetAttribute(k_ctx,    cudaFuncAttributeMaxDynamicSharedMemorySize, SMEM_DYN);
    cudaFuncSetAttribute(k_out,    cudaFuncAttributeMaxDynamicSharedMemorySize, SMEM_DYN);

    // launch order arranged so launch #4 (ncu capture slot) is a K=4096 GEMM
    knv_kernel<<<H, DK>>>(x, Wk, bk, Wv, bv);                         // 1
    conv_x<<<(SQ * DM) / 256, 256>>>(x);                              // 2
    tconv_wq<<<dim3(DK / 32, DM / 32, H), dim3(32, 8)>>>(Wq);         // 3
    k_qproj<<<dim3(H, SQ / 128), 256, SMEM_DYN>>>(bq);                // 4  <- profiled
    conv_keys<<<(H * LTOT * DK) / 256, 256>>>(kc, pos);               // 5
    k_scores<<<dim3(LTOT / 128, SQ / 128, H), 256, SMEM_DYN>>>();     // 6
    colsum_kernel<<<(H * LTOT) / 256, 256>>>();                       // 7
    tconv_vt<<<dim3(DK / 32, LTOT / 32, H), dim3(32, 8)>>>(vc, pos);  // 8
    k_ctx<<<dim3(SQ / 128, H), 256, SMEM_DYN>>>();                    // 9
    tconv_wo<<<dim3(DM / 32, DM / 32), dim3(32, 8)>>>(Wo);            // 10
    k_out<<<dim3(DM / 128, SQ / 128), 256, SMEM_DYN>>>(bo, out);      // 11
}